// round 17
// baseline (speedup 1.0000x reference)
#include <cuda_runtime.h>
#include <cuda_bf16.h>
#include <cstdint>

#define MAXN 50000
#define MAXE 800000
typedef __nv_bfloat16 bf16;

// ---------------- scratch (device globals; no allocation allowed) ----------------
__device__ __align__(16) bf16 g_xl1b[(size_t)MAXN * 256];
__device__ __align__(16) bf16 g_xr1b[(size_t)MAXN * 256];
__device__ __align__(16) bf16 g_xl2b[(size_t)MAXN * 64];
__device__ __align__(16) bf16 g_xr2b[(size_t)MAXN * 64];
__device__ __align__(16) bf16 g_hb[(size_t)MAXN * 256];
// weight transposes [n][k], SPLIT bf16: w1l@0 (256x128), w1r@32768, w2l@65536 (64x256), w2r@81920
__device__ __align__(16) bf16 g_wthi[98304];
__device__ __align__(16) bf16 g_wtlo[98304];
__device__ int g_deg[MAXN];
__device__ int g_rowptr[MAXN + 1];
__device__ int g_woff[MAXN];
__device__ int g_csr_src[MAXE];
__device__ int g_bsum[256];
__device__ float g_acc[64];
__device__ float g_cnt[64];

__device__ __forceinline__ float lrelu(float v) { return v > 0.f ? v : 0.2f * v; }

__device__ __forceinline__ uint32_t smem_u32(const void* p) {
    uint32_t a;
    asm("{ .reg .u64 t; cvta.to.shared.u64 t, %1; cvt.u32.u64 %0, t; }" : "=r"(a) : "l"(p));
    return a;
}
__device__ __forceinline__ void cp16(uint32_t s, const void* g) {
    asm volatile("cp.async.cg.shared.global [%0], [%1], 16;" :: "r"(s), "l"(g));
}
#define CP_COMMIT() asm volatile("cp.async.commit_group;" ::: "memory")
#define LDSM4(r0, r1, r2, r3, addr) \
    asm volatile("ldmatrix.sync.aligned.m8n8.x4.shared.b16 {%0,%1,%2,%3}, [%4];" \
                 : "=r"(r0), "=r"(r1), "=r"(r2), "=r"(r3) : "r"(addr))

__device__ __forceinline__ void mma_bf16(float* d, const uint32_t* a, const uint32_t* b) {
    asm volatile("mma.sync.aligned.m16n8k16.row.col.f32.bf16.bf16.f32 "
                 "{%0,%1,%2,%3}, {%4,%5,%6,%7}, {%8,%9}, {%0,%1,%2,%3};"
                 : "+f"(d[0]), "+f"(d[1]), "+f"(d[2]), "+f"(d[3])
                 : "r"(a[0]), "r"(a[1]), "r"(a[2]), "r"(a[3]), "r"(b[0]), "r"(b[1]));
}

// ---------------- side-stream prep: init + histogram + graph counts --------------
__global__ void init0(int N) {
    int i = blockIdx.x * blockDim.x + threadIdx.x;
    if (i < N) g_deg[i] = 0;
    if (i < 64) { g_acc[i] = 0.f; g_cnt[i] = 0.f; }
}
__global__ void hist_kernel(const int* __restrict__ dst, const int* __restrict__ batch,
                            int N, int E) {
    int i = blockIdx.x * blockDim.x + threadIdx.x;
    if (i < E) atomicAdd(&g_deg[dst[i]], 1);
    if (i < N) atomicAdd(&g_cnt[batch[i]], 1.f);
}

// weight transposes, SPLIT bf16 hi/lo
__global__ void split_wt_all(const float* __restrict__ Wl1, const float* __restrict__ Wr1,
                             const float* __restrict__ Wl2, const float* __restrict__ Wr2) {
    int i = blockIdx.x * blockDim.x + threadIdx.x;
    if (i >= 98304) return;
    const float* W;
    int K, Nout, off, j;
    if (i < 32768)      { W = Wl1; K = 128; Nout = 256; off = 0;     j = i; }
    else if (i < 65536) { W = Wr1; K = 128; Nout = 256; off = 32768; j = i - 32768; }
    else if (i < 81920) { W = Wl2; K = 256; Nout = 64;  off = 65536; j = i - 65536; }
    else                { W = Wr2; K = 256; Nout = 64;  off = 81920; j = i - 81920; }
    int k = j / Nout, n = j % Nout;
    float v = W[j];
    bf16 h = __float2bfloat16(v);
    g_wthi[off + n * K + k] = h;
    g_wtlo[off + n * K + k] = __float2bfloat16(v - __bfloat162float(h));
}

// ---------------- layer-1 GEMM: A (fp32->bf16 in-kernel) resident; 8 B chunks ----
// chunks 0-3: z=0 (xl, 2-term hi+lo); chunks 4-7: z=1 (xr, 1-term hi; score-only)
__global__ void __launch_bounds__(256) mma_gemm1(const float* __restrict__ x, int M)
{
    constexpr int SA = 136;
    constexpr int A_OFF = 0;
    constexpr int BUF0 = 34816;
    constexpr int BUFSZ = 34816;
    extern __shared__ char smem[];
    uint32_t sb = smem_u32(smem);
    int tid = threadIdx.x;
    int wid = tid >> 5, lane = tid & 31;
    int m0 = blockIdx.x * 128;

    auto load_b = [&](int c, int b) {
        int z = c >> 2;
        const bf16* WH = g_wthi + (z ? 32768 : 0) + (size_t)(c & 3) * 64 * 128;
        const bf16* WL = g_wtlo + (z ? 32768 : 0) + (size_t)(c & 3) * 64 * 128;
        uint32_t bbase = sb + BUF0 + b * BUFSZ;
        for (int t = tid; t < 64 * 16; t += 256) {
            int n = t >> 4, kcl = (t & 15) * 8;
            uint32_t ta = (uint32_t)(n * SA + kcl) * 2;
            cp16(bbase + ta, WH + (size_t)n * 128 + kcl);
            if (z == 0) cp16(bbase + 17408 + ta, WL + (size_t)n * 128 + kcl);
        }
        CP_COMMIT();
    };

    load_b(0, 0);
    load_b(1, 1);

    for (int c = tid; c < 128 * 16; c += 256) {
        int row = c >> 4, kcl = (c & 15) * 8;
        int rg = min(m0 + row, M - 1);
        const float4* xp = (const float4*)(x + (size_t)rg * 128 + kcl);
        float4 v0 = xp[0], v1 = xp[1];
        bf16 h8[8];
        h8[0] = __float2bfloat16(v0.x); h8[1] = __float2bfloat16(v0.y);
        h8[2] = __float2bfloat16(v0.z); h8[3] = __float2bfloat16(v0.w);
        h8[4] = __float2bfloat16(v1.x); h8[5] = __float2bfloat16(v1.y);
        h8[6] = __float2bfloat16(v1.z); h8[7] = __float2bfloat16(v1.w);
        *(uint4*)(smem + A_OFF + (uint32_t)(row * SA + kcl) * 2) = *(uint4*)h8;
    }

    int mwarp = (wid & 3) * 32;
    int nwarp = (wid >> 2) * 32;
    int sel = lane >> 3, r8 = lane & 7;
    uint32_t aoff[2], boff[2];
    #pragma unroll
    for (int mt = 0; mt < 2; mt++)
        aoff[mt] = (uint32_t)(((mwarp + mt * 16 + (sel & 1) * 8 + r8) * SA + (sel >> 1) * 8) * 2);
    #pragma unroll
    for (int bt = 0; bt < 2; bt++)
        boff[bt] = (uint32_t)(((nwarp + bt * 16 + (sel >> 1) * 8 + r8) * SA + (sel & 1) * 8) * 2);

    int g4 = lane >> 2, tig = lane & 3;

    for (int c = 0; c < 8; c++) {
        if (c < 7) asm volatile("cp.async.wait_group 1;" ::: "memory");
        else       asm volatile("cp.async.wait_group 0;" ::: "memory");
        __syncthreads();

        bool twoterm = (c < 4);
        uint32_t bb = sb + BUF0 + (c & 1) * BUFSZ;
        float d[2][4][4];
        #pragma unroll
        for (int mt = 0; mt < 2; mt++)
            #pragma unroll
            for (int nt = 0; nt < 4; nt++)
                #pragma unroll
                for (int j = 0; j < 4; j++) d[mt][nt][j] = 0.f;

        #pragma unroll
        for (int ks = 0; ks < 8; ks++) {
            uint32_t kb = ks * 32;
            uint32_t ah[2][4], bh[8], bl[8];
            #pragma unroll
            for (int mt = 0; mt < 2; mt++)
                LDSM4(ah[mt][0], ah[mt][1], ah[mt][2], ah[mt][3], sb + A_OFF + aoff[mt] + kb);
            #pragma unroll
            for (int bt = 0; bt < 2; bt++)
                LDSM4(bh[bt*4], bh[bt*4+1], bh[bt*4+2], bh[bt*4+3], bb + boff[bt] + kb);
            if (twoterm) {
                #pragma unroll
                for (int bt = 0; bt < 2; bt++)
                    LDSM4(bl[bt*4], bl[bt*4+1], bl[bt*4+2], bl[bt*4+3], bb + 17408 + boff[bt] + kb);
            }
            #pragma unroll
            for (int mt = 0; mt < 2; mt++)
                #pragma unroll
                for (int nt = 0; nt < 4; nt++) {
                    mma_bf16(d[mt][nt], ah[mt], &bh[nt * 2]);
                    if (twoterm) mma_bf16(d[mt][nt], ah[mt], &bl[nt * 2]);
                }
        }
        __syncthreads();

        if (c + 2 < 8) load_b(c + 2, c & 1);

        int z = c >> 2;
        int colb = (c & 3) * 64;
        bf16* Cb = z ? g_xr1b : g_xl1b;
        #pragma unroll
        for (int mt = 0; mt < 2; mt++) {
            int mrow = m0 + mwarp + mt * 16 + g4;
            #pragma unroll
            for (int nt = 0; nt < 4; nt++) {
                int col = colb + nwarp + nt * 8 + tig * 2;
                if (mrow < M) {
                    __nv_bfloat162 p = __float22bfloat162_rn(make_float2(d[mt][nt][0], d[mt][nt][1]));
                    *(uint32_t*)(Cb + (size_t)mrow * 256 + col) = *(uint32_t*)&p;
                }
                if (mrow + 8 < M) {
                    __nv_bfloat162 p = __float22bfloat162_rn(make_float2(d[mt][nt][2], d[mt][nt][3]));
                    *(uint32_t*)(Cb + (size_t)(mrow + 8) * 256 + col) = *(uint32_t*)&p;
                }
            }
        }
    }
}

// ---------------- CSR build: coalesced 3-stage scan ----------------
__global__ void blocksum_kernel(int N) {
    __shared__ int sh[256];
    int tid = threadIdx.x;
    int i = blockIdx.x * 256 + tid;
    sh[tid] = (i < N) ? g_deg[i] : 0;
    __syncthreads();
    for (int s = 128; s > 0; s >>= 1) {
        if (tid < s) sh[tid] += sh[tid + s];
        __syncthreads();
    }
    if (tid == 0) g_bsum[blockIdx.x] = sh[0];
}
__global__ void scanb_kernel(int nb) {
    __shared__ int sh[256];
    int tid = threadIdx.x;
    int v = (tid < nb) ? g_bsum[tid] : 0;
    sh[tid] = v;
    __syncthreads();
    for (int s = 1; s < 256; s <<= 1) {
        int t = (tid >= s) ? sh[tid - s] : 0;
        __syncthreads();
        sh[tid] += t;
        __syncthreads();
    }
    if (tid < nb) g_bsum[tid] = sh[tid] - v;
}
__global__ void rowptr_kernel(int N, int E) {
    __shared__ int sh[256];
    int tid = threadIdx.x;
    int i = blockIdx.x * 256 + tid;
    int v = (i < N) ? g_deg[i] : 0;
    sh[tid] = v;
    __syncthreads();
    for (int s = 1; s < 256; s <<= 1) {
        int t = (tid >= s) ? sh[tid - s] : 0;
        __syncthreads();
        sh[tid] += t;
        __syncthreads();
    }
    if (i < N) {
        int ex = g_bsum[blockIdx.x] + sh[tid] - v;
        g_rowptr[i] = ex;
        g_woff[i] = ex;
        if (i == N - 1) g_rowptr[N] = E;
    }
}
__global__ void scatter_kernel(const int* __restrict__ src, const int* __restrict__ dst, int E) {
    int e = blockIdx.x * blockDim.x + threadIdx.x;
    if (e >= E) return;
    int pos = atomicAdd(&g_woff[dst[e]], 1);
    g_csr_src[pos] = src[e];
}

// ---------------- layer-2 GEMM: K pipelined in 4x64 chunks; z1 hi-only ------------
__global__ void __launch_bounds__(256) mma_gemm2(int M)
{
    constexpr int SA = 72;
    constexpr int BBYT = 9216;
    constexpr int B_OFF = 18432;
    constexpr int BUFSZ = 46080;
    extern __shared__ char smem[];
    uint32_t sb = smem_u32(smem);
    int tid = threadIdx.x;
    int wid = tid >> 5, lane = tid & 31;
    int m0 = blockIdx.x * 128;

    auto load_chunk = [&](int kc, int b) {
        uint32_t base = sb + b * BUFSZ;
        for (int c = tid; c < 128 * 8; c += 256) {
            int row = c >> 3, kcl = (c & 7) * 8;
            int rg = min(m0 + row, M - 1);
            cp16(base + (uint32_t)(row * SA + kcl) * 2, g_hb + (size_t)rg * 256 + kc * 64 + kcl);
        }
        for (int c = tid; c < 3 * 64 * 8; c += 256) {
            int part = c >> 9, r = c & 511;
            int n = r >> 3, kcl = (r & 7) * 8;
            const bf16* W = (part == 0) ? (g_wthi + 65536)
                          : (part == 1) ? (g_wtlo + 65536)
                                        : (g_wthi + 81920);
            cp16(base + B_OFF + part * BBYT + (uint32_t)(n * SA + kcl) * 2,
                 W + (size_t)n * 256 + kc * 64 + kcl);
        }
        CP_COMMIT();
    };

    load_chunk(0, 0);

    int mwarp = (wid & 3) * 32;
    int nwarp = (wid >> 2) * 32;
    int sel = lane >> 3, r8 = lane & 7;
    uint32_t aoff[2], boff[2];
    #pragma unroll
    for (int mt = 0; mt < 2; mt++)
        aoff[mt] = (uint32_t)(((mwarp + mt * 16 + (sel & 1) * 8 + r8) * SA + (sel >> 1) * 8) * 2);
    #pragma unroll
    for (int bt = 0; bt < 2; bt++)
        boff[bt] = (uint32_t)(((nwarp + bt * 16 + (sel >> 1) * 8 + r8) * SA + (sel & 1) * 8) * 2);

    float d[2][2][4][4];
    #pragma unroll
    for (int z = 0; z < 2; z++)
        #pragma unroll
        for (int mt = 0; mt < 2; mt++)
            #pragma unroll
            for (int nt = 0; nt < 4; nt++)
                #pragma unroll
                for (int j = 0; j < 4; j++) d[z][mt][nt][j] = 0.f;

    for (int kc = 0; kc < 4; kc++) {
        if (kc < 3) {
            load_chunk(kc + 1, (kc + 1) & 1);
            asm volatile("cp.async.wait_group 1;" ::: "memory");
        } else {
            asm volatile("cp.async.wait_group 0;" ::: "memory");
        }
        __syncthreads();
        uint32_t base = sb + (kc & 1) * BUFSZ;

        #pragma unroll
        for (int ks = 0; ks < 4; ks++) {
            uint32_t kb = ks * 32;
            uint32_t ah[2][4], b0h[8], b0l[8], b1h[8];
            #pragma unroll
            for (int mt = 0; mt < 2; mt++)
                LDSM4(ah[mt][0], ah[mt][1], ah[mt][2], ah[mt][3], base + aoff[mt] + kb);
            #pragma unroll
            for (int bt = 0; bt < 2; bt++) {
                LDSM4(b0h[bt*4], b0h[bt*4+1], b0h[bt*4+2], b0h[bt*4+3], base + B_OFF + boff[bt] + kb);
                LDSM4(b0l[bt*4], b0l[bt*4+1], b0l[bt*4+2], b0l[bt*4+3], base + B_OFF + BBYT + boff[bt] + kb);
                LDSM4(b1h[bt*4], b1h[bt*4+1], b1h[bt*4+2], b1h[bt*4+3], base + B_OFF + 2*BBYT + boff[bt] + kb);
            }
            #pragma unroll
            for (int mt = 0; mt < 2; mt++)
                #pragma unroll
                for (int nt = 0; nt < 4; nt++) {
                    mma_bf16(d[0][mt][nt], ah[mt], &b0h[nt * 2]);
                    mma_bf16(d[0][mt][nt], ah[mt], &b0l[nt * 2]);
                    mma_bf16(d[1][mt][nt], ah[mt], &b1h[nt * 2]);
                }
        }
        __syncthreads();
    }

    int g4 = lane >> 2, tig = lane & 3;
    #pragma unroll
    for (int z = 0; z < 2; z++) {
        bf16* Cb = z ? g_xr2b : g_xl2b;
        #pragma unroll
        for (int mt = 0; mt < 2; mt++) {
            int mrow = m0 + mwarp + mt * 16 + g4;
            #pragma unroll
            for (int nt = 0; nt < 4; nt++) {
                int col = nwarp + nt * 8 + tig * 2;
                if (mrow < M) {
                    __nv_bfloat162 p = __float22bfloat162_rn(make_float2(d[z][mt][nt][0], d[z][mt][nt][1]));
                    *(uint32_t*)(Cb + (size_t)mrow * 64 + col) = *(uint32_t*)&p;
                }
                if (mrow + 8 < M) {
                    __nv_bfloat162 p = __float22bfloat162_rn(make_float2(d[z][mt][nt][2], d[z][mt][nt][3]));
                    *(uint32_t*)(Cb + (size_t)(mrow + 8) * 64 + col) = *(uint32_t*)&p;
                }
            }
        }
    }
}

// ---------------- layer 1 fused attention: warp/dst, 4-edge ILP, reg-staged idx --
__global__ void gat1_kernel(const float* __restrict__ att, const float* __restrict__ b1, int N)
{
    int d = (blockIdx.x * blockDim.x + threadIdx.x) >> 5;
    if (d >= N) return;
    int lane = threadIdx.x & 31;
    int off = lane * 8;

    uint4 xrr = *(const uint4*)(g_xr1b + (size_t)d * 256 + off);
    float2 xr0 = __bfloat1622float2(*(__nv_bfloat162*)&xrr.x);
    float2 xr1 = __bfloat1622float2(*(__nv_bfloat162*)&xrr.y);
    float2 xr2 = __bfloat1622float2(*(__nv_bfloat162*)&xrr.z);
    float2 xr3 = __bfloat1622float2(*(__nv_bfloat162*)&xrr.w);
    float4 aw0 = *(const float4*)(att + off);
    float4 aw1 = *(const float4*)(att + off + 4);

    float num[8];
    #pragma unroll
    for (int j = 0; j < 8; j++) num[j] = 0.f;
    float den = 0.f;

    int lo = g_rowptr[d], hi = g_rowptr[d + 1];
    int cnt = hi - lo + 1;   // + self loop (last slot)

    // warp-coalesced index staging: lane l holds index for edge blk*32 + l
    auto loadIdx = [&](int b) {
        int pos = lo + b * 32 + lane;
        return (pos < hi) ? g_csr_src[pos] : d;   // OOB slots = self (safe addr)
    };
    int blk = 0;
    int idxA = loadIdx(0), idxB = loadIdx(1);
    auto srcOf = [&](int i) {
        int v = ((i >> 5) == blk) ? idxA : idxB;
        return __shfl_sync(0xffffffffu, v, i & 31);
    };
    auto ldi = [&](int i) { return *(const uint4*)(g_xl1b + (size_t)srcOf(i) * 256 + off); };
    auto scoreOf = [&](uint4 cc) {
        float2 f0 = __bfloat1622float2(*(__nv_bfloat162*)&cc.x);
        float2 f1 = __bfloat1622float2(*(__nv_bfloat162*)&cc.y);
        float2 f2 = __bfloat1622float2(*(__nv_bfloat162*)&cc.z);
        float2 f3 = __bfloat1622float2(*(__nv_bfloat162*)&cc.w);
        return lrelu(f0.x + xr0.x) * aw0.x + lrelu(f0.y + xr0.y) * aw0.y
             + lrelu(f1.x + xr1.x) * aw0.z + lrelu(f1.y + xr1.y) * aw0.w
             + lrelu(f2.x + xr2.x) * aw1.x + lrelu(f2.y + xr2.y) * aw1.y
             + lrelu(f3.x + xr3.x) * aw1.z + lrelu(f3.y + xr3.y) * aw1.w;
    };
    auto accum = [&](uint4 cc, float e) {
        float2 f0 = __bfloat1622float2(*(__nv_bfloat162*)&cc.x);
        float2 f1 = __bfloat1622float2(*(__nv_bfloat162*)&cc.y);
        float2 f2 = __bfloat1622float2(*(__nv_bfloat162*)&cc.z);
        float2 f3 = __bfloat1622float2(*(__nv_bfloat162*)&cc.w);
        num[0] += e * f0.x; num[1] += e * f0.y; num[2] += e * f1.x; num[3] += e * f1.y;
        num[4] += e * f2.x; num[5] += e * f2.y; num[6] += e * f3.x; num[7] += e * f3.y;
    };

    uint4 v0 = ldi(0), v1 = ldi(1), v2 = ldi(2), v3 = ldi(3);

    int i = 0;
    for (; i + 3 < cnt; i += 4) {
        if ((i >> 5) != blk) { blk = i >> 5; idxA = idxB; idxB = loadIdx(blk + 1); }
        uint4 c0 = v0, c1 = v1, c2 = v2, c3 = v3;
        v0 = ldi(i + 4); v1 = ldi(i + 5); v2 = ldi(i + 6); v3 = ldi(i + 7);
        float p0 = scoreOf(c0), p1 = scoreOf(c1), p2 = scoreOf(c2), p3 = scoreOf(c3);
        p0 += __shfl_xor_sync(0xffffffffu, p0, 1);
        p1 += __shfl_xor_sync(0xffffffffu, p1, 1);
        p2 += __shfl_xor_sync(0xffffffffu, p2, 1);
        p3 += __shfl_xor_sync(0xffffffffu, p3, 1);
        p0 += __shfl_xor_sync(0xffffffffu, p0, 2);
        p1 += __shfl_xor_sync(0xffffffffu, p1, 2);
        p2 += __shfl_xor_sync(0xffffffffu, p2, 2);
        p3 += __shfl_xor_sync(0xffffffffu, p3, 2);
        p0 += __shfl_xor_sync(0xffffffffu, p0, 4);
        p1 += __shfl_xor_sync(0xffffffffu, p1, 4);
        p2 += __shfl_xor_sync(0xffffffffu, p2, 4);
        p3 += __shfl_xor_sync(0xffffffffu, p3, 4);
        float e0 = __expf(p0), e1 = __expf(p1), e2 = __expf(p2), e3 = __expf(p3);
        den += (e0 + e1) + (e2 + e3);
        accum(c0, e0); accum(c1, e1); accum(c2, e2); accum(c3, e3);
    }
    for (int t = 0; i < cnt; i++, t++) {
        uint4 c0 = (t == 0) ? v0 : (t == 1) ? v1 : (t == 2) ? v2 : v3;
        float p0 = scoreOf(c0);
        p0 += __shfl_xor_sync(0xffffffffu, p0, 1);
        p0 += __shfl_xor_sync(0xffffffffu, p0, 2);
        p0 += __shfl_xor_sync(0xffffffffu, p0, 4);
        float e0 = __expf(p0);
        den += e0;
        accum(c0, e0);
    }

    float inv = 1.f / (den + 1e-16f);
    float4 bb0 = *(const float4*)(b1 + off);
    float4 bb1 = *(const float4*)(b1 + off + 4);
    float bias[8] = {bb0.x, bb0.y, bb0.z, bb0.w, bb1.x, bb1.y, bb1.z, bb1.w};
    bf16 h8[8];
    #pragma unroll
    for (int j = 0; j < 8; j++)
        h8[j] = __float2bfloat16(fmaxf(num[j] * inv + bias[j], 0.f));
    *(uint4*)(g_hb + (size_t)d * 256 + off) = *(uint4*)h8;
}

// ---------------- layer 2 fused attention + pooling: 4-edge ILP, reg-staged idx --
__global__ void gat2_kernel(const float* __restrict__ att, const int* __restrict__ batch,
                            const float* __restrict__ b2, const float* __restrict__ Wo, int N)
{
    int d = (blockIdx.x * blockDim.x + threadIdx.x) >> 5;
    if (d >= N) return;
    int lane = threadIdx.x & 31;
    int off = lane * 2;

    uint32_t xrr = *(const uint32_t*)(g_xr2b + (size_t)d * 64 + off);
    float2 xr = __bfloat1622float2(*(__nv_bfloat162*)&xrr);
    float2 aw = *(const float2*)(att + off);

    float num0 = 0.f, num1 = 0.f, den = 0.f;
    int lo = g_rowptr[d], hi = g_rowptr[d + 1];
    int cnt = hi - lo + 1;

    auto loadIdx = [&](int b) {
        int pos = lo + b * 32 + lane;
        return (pos < hi) ? g_csr_src[pos] : d;
    };
    int blk = 0;
    int idxA = loadIdx(0), idxB = loadIdx(1);
    auto srcOf = [&](int i) {
        int v = ((i >> 5) == blk) ? idxA : idxB;
        return __shfl_sync(0xffffffffu, v, i & 31);
    };
    auto ldi = [&](int i) { return *(const uint32_t*)(g_xl2b + (size_t)srcOf(i) * 64 + off); };
    auto scoreOf = [&](uint32_t cc) {
        float2 xv = __bfloat1622float2(*(__nv_bfloat162*)&cc);
        return lrelu(xv.x + xr.x) * aw.x + lrelu(xv.y + xr.y) * aw.y;
    };
    auto accum = [&](uint32_t cc, float e) {
        float2 xv = __bfloat1622float2(*(__nv_bfloat162*)&cc);
        num0 += e * xv.x;
        num1 += e * xv.y;
    };

    uint32_t v0 = ldi(0), v1 = ldi(1), v2 = ldi(2), v3 = ldi(3);

    int i = 0;
    for (; i + 3 < cnt; i += 4) {
        if ((i >> 5) != blk) { blk = i >> 5; idxA = idxB; idxB = loadIdx(blk + 1); }
        uint32_t c0 = v0, c1 = v1, c2 = v2, c3 = v3;
        v0 = ldi(i + 4); v1 = ldi(i + 5); v2 = ldi(i + 6); v3 = ldi(i + 7);
        float p0 = scoreOf(c0), p1 = scoreOf(c1), p2 = scoreOf(c2), p3 = scoreOf(c3);
        #pragma unroll
        for (int s = 1; s < 32; s <<= 1) {
            p0 += __shfl_xor_sync(0xffffffffu, p0, s);
            p1 += __shfl_xor_sync(0xffffffffu, p1, s);
            p2 += __shfl_xor_sync(0xffffffffu, p2, s);
            p3 += __shfl_xor_sync(0xffffffffu, p3, s);
        }
        float e0 = __expf(p0), e1 = __expf(p1), e2 = __expf(p2), e3 = __expf(p3);
        den += (e0 + e1) + (e2 + e3);
        accum(c0, e0); accum(c1, e1); accum(c2, e2); accum(c3, e3);
    }
    for (int t = 0; i < cnt; i++, t++) {
        uint32_t c0 = (t == 0) ? v0 : (t == 1) ? v1 : (t == 2) ? v2 : v3;
        float p0 = scoreOf(c0);
        #pragma unroll
        for (int s = 1; s < 32; s <<= 1)
            p0 += __shfl_xor_sync(0xffffffffu, p0, s);
        float e0 = __expf(p0);
        den += e0;
        accum(c0, e0);
    }

    float inv = 1.f / (den + 1e-16f);
    float2 bb = *(const float2*)(b2 + off);
    float2 wo = *(const float2*)(Wo + off);
    float y = (num0 * inv + bb.x) * wo.x + (num1 * inv + bb.y) * wo.y;
    y += __shfl_xor_sync(0xffffffffu, y, 1);
    y += __shfl_xor_sync(0xffffffffu, y, 2);
    y += __shfl_xor_sync(0xffffffffu, y, 4);
    y += __shfl_xor_sync(0xffffffffu, y, 8);
    y += __shfl_xor_sync(0xffffffffu, y, 16);
    if (lane == 0) atomicAdd(&g_acc[batch[d]], y);
}

__global__ void final_kernel(float* __restrict__ out, int G, const float* __restrict__ bo)
{
    int g = threadIdx.x;
    if (g < G) out[g] = g_acc[g] / fmaxf(g_cnt[g], 1.f) + bo[0];
}

// ---------------- launch: gemm1 starts immediately; all prep on side stream ------
extern "C" void kernel_launch(void* const* d_in, const int* in_sizes, int n_in,
                              void* d_out, int out_size)
{
    const float* x    = (const float*)d_in[0];
    const int* ei     = (const int*)d_in[1];
    const int* bat    = (const int*)d_in[2];
    const float* Wl1 = (const float*)d_in[3];
    const float* Wr1 = (const float*)d_in[4];
    const float* att1 = (const float*)d_in[5];
    const float* b1  = (const float*)d_in[6];
    const float* Wl2 = (const float*)d_in[7];
    const float* Wr2 = (const float*)d_in[8];
    const float* att2 = (const float*)d_in[9];
    const float* b2  = (const float*)d_in[10];
    const float* Wo  = (const float*)d_in[11];
    const float* bo  = (const float*)d_in[12];

    int N = in_sizes[0] / 128;
    int E = in_sizes[1] / 2;
    int G = out_size;
    const int* src = ei;
    const int* dst = ei + E;
    int tiles = (N + 127) / 128;
    int nb = (N + 255) / 256;

    const int SM1 = 34816 + 2 * 34816;
    const int SM2 = 2 * 46080;

    static bool inited = false;
    static cudaStream_t s2;
    static cudaEvent_t ev0, ev_csr;
    if (!inited) {
        cudaStreamCreateWithFlags(&s2, cudaStreamNonBlocking);
        cudaEventCreateWithFlags(&ev0, cudaEventDisableTiming);
        cudaEventCreateWithFlags(&ev_csr, cudaEventDisableTiming);
        cudaFuncSetAttribute(mma_gemm1, cudaFuncAttributeMaxDynamicSharedMemorySize, SM1);
        cudaFuncSetAttribute(mma_gemm2, cudaFuncAttributeMaxDynamicSharedMemorySize, SM2);
        inited = true;
    }

    cudaEventRecord(ev0, 0);
    cudaStreamWaitEvent(s2, ev0, 0);

    // main: weight split, then gemm1 (critical path)
    split_wt_all<<<(98304 + 255) / 256, 256>>>(Wl1, Wr1, Wl2, Wr2);

    // side: init + histogram + CSR (under gemm1)
    init0<<<(N + 255) / 256, 256, 0, s2>>>(N);
    hist_kernel<<<(max(N, E) + 255) / 256, 256, 0, s2>>>(dst, bat, N, E);
    blocksum_kernel<<<nb, 256, 0, s2>>>(N);
    scanb_kernel<<<1, 256, 0, s2>>>(nb);
    rowptr_kernel<<<nb, 256, 0, s2>>>(N, E);
    scatter_kernel<<<(E + 255) / 256, 256, 0, s2>>>(src, dst, E);
    cudaEventRecord(ev_csr, s2);

    mma_gemm1<<<tiles, 256, SM1>>>(x, N);

    cudaStreamWaitEvent(0, ev_csr, 0);
    gat1_kernel<<<(N * 32 + 255) / 256, 256>>>(att1, b1, N);
    mma_gemm2<<<tiles, 256, SM2>>>(N);
    gat2_kernel<<<(N * 32 + 255) / 256, 256>>>(att2, bat, b2, Wo, N);
    final_kernel<<<1, 64>>>((float*)d_out, G, bo);
}